// round 1
// baseline (speedup 1.0000x reference)
#include <cuda_runtime.h>
#include <cuda_fp16.h>
#include <cstdint>

#define BATCH 8
#define S1D 2048
#define S2D 2048
#define EDIM 1024
#define PDIM 1024

#define BM 128
#define BN 128
#define BK 32
#define ST 40   // smem row stride in halves (padded; conflict-free for frag loads)

// ---------------- scratch (static device allocations; no cudaMalloc allowed) ------------
__device__ __half g_qh[(size_t)BATCH * S1D * PDIM];      // 32 MB
__device__ __half g_kh[(size_t)BATCH * S2D * PDIM];      // 32 MB
__device__ __half g_vh[(size_t)BATCH * S2D * PDIM];      // 32 MB
__device__ __half g_wh[(size_t)PDIM * EDIM];             // 2 MB
__device__ float  g_scores[(size_t)BATCH * S1D * S2D];   // 134 MB
__device__ __half g_probs[(size_t)BATCH * S1D * S2D];    // 67 MB

// ---------------- mma.m16n8k16 fp16 -> fp32 ----------------
__device__ __forceinline__ void mma16816(float c[4], const uint32_t a[4], const uint32_t b[2]) {
    asm volatile(
        "mma.sync.aligned.m16n8k16.row.col.f32.f16.f16.f32 "
        "{%0,%1,%2,%3}, {%4,%5,%6,%7}, {%8,%9}, {%0,%1,%2,%3};\n"
        : "+f"(c[0]), "+f"(c[1]), "+f"(c[2]), "+f"(c[3])
        : "r"(a[0]), "r"(a[1]), "r"(a[2]), "r"(a[3]), "r"(b[0]), "r"(b[1]));
}

// Shared compute: As [BM][ST] (m-major, k contiguous), Bs [BN][ST] (n-major, k contiguous).
// Warp tile 32(m) x 64(n): 2 m-frags x 8 n-frags.
__device__ __forceinline__ void mma_tile(const __half* As, const __half* Bs,
                                         int wm, int wn, int g, int t,
                                         float c[2][8][4]) {
#pragma unroll
    for (int kk = 0; kk < BK; kk += 16) {
        uint32_t a[2][4];
#pragma unroll
        for (int i = 0; i < 2; i++) {
            int m = wm + 16 * i;
            a[i][0] = *(const uint32_t*)&As[(m + g) * ST + kk + 2 * t];
            a[i][1] = *(const uint32_t*)&As[(m + g + 8) * ST + kk + 2 * t];
            a[i][2] = *(const uint32_t*)&As[(m + g) * ST + kk + 2 * t + 8];
            a[i][3] = *(const uint32_t*)&As[(m + g + 8) * ST + kk + 2 * t + 8];
        }
#pragma unroll
        for (int j = 0; j < 8; j++) {
            int n = wn + 8 * j + g;
            uint32_t b[2];
            b[0] = *(const uint32_t*)&Bs[n * ST + kk + 2 * t];
            b[1] = *(const uint32_t*)&Bs[n * ST + kk + 2 * t + 8];
#pragma unroll
            for (int i = 0; i < 2; i++) mma16816(c[i][j], a[i], b);
        }
    }
}

__device__ __forceinline__ uint32_t h2_as_u32(__half2 h) {
    return *reinterpret_cast<uint32_t*>(&h);
}

// ---------------- W fp32 -> fp16 ----------------
__global__ void __launch_bounds__(256) convw_kernel(const float* __restrict__ W) {
    size_t i = ((size_t)blockIdx.x * 256 + threadIdx.x) * 4;
    float4 v = *(const float4*)(W + i);
    __half2 h0 = __floats2half2_rn(v.x, v.y);
    __half2 h1 = __floats2half2_rn(v.z, v.w);
    *(uint2*)(g_wh + i) = make_uint2(h2_as_u32(h0), h2_as_u32(h1));
}

// ---------------- projection: C[m][n] = sum_e A[m][e]*W[n][e] + bias[n] ----------------
// A fp32 [M][EDIM] (converted on the fly), B = g_wh fp16 [PDIM][EDIM], C fp16 [M][PDIM]
__global__ void __launch_bounds__(256) proj_kernel(const float* __restrict__ A,
                                                   const float* __restrict__ bias,
                                                   int sel) {
    __half* C = sel == 0 ? g_qh : (sel == 1 ? g_kh : g_vh);
    __shared__ __half As[BM * ST];
    __shared__ __half Bs[BN * ST];
    const int m0 = blockIdx.y * BM, n0 = blockIdx.x * BN;
    const int tid = threadIdx.x;
    const int warp = tid >> 5, lane = tid & 31;
    const int wm = (warp & 3) * 32, wn = (warp >> 2) * 64;
    const int g = lane >> 2, t = lane & 3;

    float c[2][8][4] = {};

    const int ar = tid >> 3, ac = (tid & 7) * 4;   // A: 32 rows/sweep, 8 float4 per row
    const int br = tid >> 2, bc = (tid & 3) * 8;   // B: 64 rows/sweep, 4 uint4 per row

    float4 aR[4];
    uint4 bR[2];

    const int KT = EDIM / BK;
    // prefetch tile 0
#pragma unroll
    for (int s = 0; s < 4; s++)
        aR[s] = *(const float4*)(A + (size_t)(m0 + ar + 32 * s) * EDIM + ac);
#pragma unroll
    for (int s = 0; s < 2; s++)
        bR[s] = *(const uint4*)(g_wh + (size_t)(n0 + br + 64 * s) * EDIM + bc);

    for (int kt = 0; kt < KT; kt++) {
        __syncthreads();
#pragma unroll
        for (int s = 0; s < 4; s++) {
            __half2 h0 = __floats2half2_rn(aR[s].x, aR[s].y);
            __half2 h1 = __floats2half2_rn(aR[s].z, aR[s].w);
            *(uint2*)&As[(ar + 32 * s) * ST + ac] = make_uint2(h2_as_u32(h0), h2_as_u32(h1));
        }
#pragma unroll
        for (int s = 0; s < 2; s++) {
            *(uint2*)&Bs[(br + 64 * s) * ST + bc] = make_uint2(bR[s].x, bR[s].y);
            *(uint2*)&Bs[(br + 64 * s) * ST + bc + 4] = make_uint2(bR[s].z, bR[s].w);
        }
        __syncthreads();
        if (kt + 1 < KT) {
            int ko = (kt + 1) * BK;
#pragma unroll
            for (int s = 0; s < 4; s++)
                aR[s] = *(const float4*)(A + (size_t)(m0 + ar + 32 * s) * EDIM + ko + ac);
#pragma unroll
            for (int s = 0; s < 2; s++)
                bR[s] = *(const uint4*)(g_wh + (size_t)(n0 + br + 64 * s) * EDIM + ko + bc);
        }
        mma_tile(As, Bs, wm, wn, g, t, c);
    }

#pragma unroll
    for (int i = 0; i < 2; i++)
#pragma unroll
        for (int j = 0; j < 8; j++) {
            int row = m0 + wm + 16 * i + g;
            int col = n0 + wn + 8 * j + 2 * t;
            float b0 = bias[col], b1 = bias[col + 1];
            __half2 v0 = __floats2half2_rn(c[i][j][0] + b0, c[i][j][1] + b1);
            __half2 v1 = __floats2half2_rn(c[i][j][2] + b0, c[i][j][3] + b1);
            *(__half2*)(C + (size_t)row * PDIM + col) = v0;
            *(__half2*)(C + (size_t)(row + 8) * PDIM + col) = v1;
        }
}

// ---------------- scores: S[b][q][k] = (1/32) * sum_p Qp[q,p]*Kp[k,p] ----------------
__global__ void __launch_bounds__(256) scores_kernel() {
    const __half* Aq = g_qh + (size_t)blockIdx.z * S1D * PDIM;
    const __half* Bk = g_kh + (size_t)blockIdx.z * S2D * PDIM;
    float* C = g_scores + (size_t)blockIdx.z * S1D * S2D;
    __shared__ __half As[BM * ST];
    __shared__ __half Bs[BN * ST];
    const int m0 = blockIdx.y * BM, n0 = blockIdx.x * BN;
    const int tid = threadIdx.x;
    const int warp = tid >> 5, lane = tid & 31;
    const int wm = (warp & 3) * 32, wn = (warp >> 2) * 64;
    const int g = lane >> 2, t = lane & 3;

    float c[2][8][4] = {};

    const int r = tid >> 2, cc = (tid & 3) * 8;   // both tiles: 128 rows x 32 halves

    uint4 aR[2], bR[2];
    const int KT = PDIM / BK;
#pragma unroll
    for (int s = 0; s < 2; s++) {
        aR[s] = *(const uint4*)(Aq + (size_t)(m0 + r + 64 * s) * PDIM + cc);
        bR[s] = *(const uint4*)(Bk + (size_t)(n0 + r + 64 * s) * PDIM + cc);
    }

    for (int kt = 0; kt < KT; kt++) {
        __syncthreads();
#pragma unroll
        for (int s = 0; s < 2; s++) {
            *(uint2*)&As[(r + 64 * s) * ST + cc] = make_uint2(aR[s].x, aR[s].y);
            *(uint2*)&As[(r + 64 * s) * ST + cc + 4] = make_uint2(aR[s].z, aR[s].w);
            *(uint2*)&Bs[(r + 64 * s) * ST + cc] = make_uint2(bR[s].x, bR[s].y);
            *(uint2*)&Bs[(r + 64 * s) * ST + cc + 4] = make_uint2(bR[s].z, bR[s].w);
        }
        __syncthreads();
        if (kt + 1 < KT) {
            int ko = (kt + 1) * BK;
#pragma unroll
            for (int s = 0; s < 2; s++) {
                aR[s] = *(const uint4*)(Aq + (size_t)(m0 + r + 64 * s) * PDIM + ko + cc);
                bR[s] = *(const uint4*)(Bk + (size_t)(n0 + r + 64 * s) * PDIM + ko + cc);
            }
        }
        mma_tile(As, Bs, wm, wn, g, t, c);
    }

    const float SC = 0.03125f;  // 1/sqrt(1024)
#pragma unroll
    for (int i = 0; i < 2; i++)
#pragma unroll
        for (int j = 0; j < 8; j++) {
            int row = m0 + wm + 16 * i + g;
            int col = n0 + wn + 8 * j + 2 * t;
            float2 v0 = make_float2(c[i][j][0] * SC, c[i][j][1] * SC);
            float2 v1 = make_float2(c[i][j][2] * SC, c[i][j][3] * SC);
            *(float2*)(C + (size_t)row * S2D + col) = v0;
            *(float2*)(C + (size_t)(row + 8) * S2D + col) = v1;
        }
}

// ---------------- softmax over last dim (2048), fp32 in -> fp16 probs ----------------
__global__ void __launch_bounds__(256) softmax_kernel() {
    const size_t row = blockIdx.x;
    const float* src = g_scores + row * S2D;
    __half* dst = g_probs + row * S2D;
    const int tid = threadIdx.x;
    const int lane = tid & 31, warp = tid >> 5;

    float4 v0 = *(const float4*)(src + tid * 4);
    float4 v1 = *(const float4*)(src + 1024 + tid * 4);

    float m = fmaxf(fmaxf(fmaxf(v0.x, v0.y), fmaxf(v0.z, v0.w)),
                    fmaxf(fmaxf(v1.x, v1.y), fmaxf(v1.z, v1.w)));
#pragma unroll
    for (int off = 16; off > 0; off >>= 1)
        m = fmaxf(m, __shfl_xor_sync(0xffffffffu, m, off));

    __shared__ float red[8];
    __shared__ float sbc;
    if (lane == 0) red[warp] = m;
    __syncthreads();
    if (warp == 0) {
        float x = (lane < 8) ? red[lane] : -1e30f;
#pragma unroll
        for (int off = 4; off > 0; off >>= 1)
            x = fmaxf(x, __shfl_xor_sync(0xffffffffu, x, off));
        if (lane == 0) sbc = x;
    }
    __syncthreads();
    m = sbc;

    float e[8];
    e[0] = expf(v0.x - m); e[1] = expf(v0.y - m); e[2] = expf(v0.z - m); e[3] = expf(v0.w - m);
    e[4] = expf(v1.x - m); e[5] = expf(v1.y - m); e[6] = expf(v1.z - m); e[7] = expf(v1.w - m);

    float s = e[0] + e[1] + e[2] + e[3] + e[4] + e[5] + e[6] + e[7];
#pragma unroll
    for (int off = 16; off > 0; off >>= 1)
        s += __shfl_xor_sync(0xffffffffu, s, off);
    __syncthreads();  // protect red[] reuse
    if (lane == 0) red[warp] = s;
    __syncthreads();
    if (warp == 0) {
        float x = (lane < 8) ? red[lane] : 0.0f;
#pragma unroll
        for (int off = 4; off > 0; off >>= 1)
            x += __shfl_xor_sync(0xffffffffu, x, off);
        if (lane == 0) sbc = x;
    }
    __syncthreads();
    float inv = 1.0f / sbc;

    __half2 h0 = __floats2half2_rn(e[0] * inv, e[1] * inv);
    __half2 h1 = __floats2half2_rn(e[2] * inv, e[3] * inv);
    __half2 h2 = __floats2half2_rn(e[4] * inv, e[5] * inv);
    __half2 h3 = __floats2half2_rn(e[6] * inv, e[7] * inv);
    *(uint2*)(dst + tid * 4) = make_uint2(h2_as_u32(h0), h2_as_u32(h1));
    *(uint2*)(dst + 1024 + tid * 4) = make_uint2(h2_as_u32(h2), h2_as_u32(h3));
}

// ---------------- output: O[b][q][p] = sum_k probs[q,k] * Vp[k,p]  (NN gemm) ----------------
__global__ void __launch_bounds__(256) out_kernel(float* __restrict__ OUT) {
    const __half* Ap = g_probs + (size_t)blockIdx.z * S1D * S2D;
    const __half* Bv = g_vh + (size_t)blockIdx.z * S2D * PDIM;
    float* C = OUT + (size_t)blockIdx.z * S1D * PDIM;
    __shared__ __half As[BM * ST];
    __shared__ __half Bs[BN * ST];
    const int m0 = blockIdx.y * BM, n0 = blockIdx.x * BN;
    const int tid = threadIdx.x;
    const int warp = tid >> 5, lane = tid & 31;
    const int wm = (warp & 3) * 32, wn = (warp >> 2) * 64;
    const int g = lane >> 2, t = lane & 3;

    float c[2][8][4] = {};

    const int ar = tid >> 2, ac = (tid & 3) * 8;    // A: 128 rows x 32 halves (k-major)
    const int bkk = tid >> 4, bc8 = (tid & 15) * 8; // B: 16 k-rows/sweep x 128 n

    uint4 aR[2], bR[2];
    const int KT = S2D / BK;
#pragma unroll
    for (int s = 0; s < 2; s++) {
        aR[s] = *(const uint4*)(Ap + (size_t)(m0 + ar + 64 * s) * S2D + ac);
        bR[s] = *(const uint4*)(Bv + (size_t)(bkk + 16 * s) * PDIM + n0 + bc8);
    }

    for (int kt = 0; kt < KT; kt++) {
        __syncthreads();
#pragma unroll
        for (int s = 0; s < 2; s++) {
            *(uint2*)&As[(ar + 64 * s) * ST + ac] = make_uint2(aR[s].x, aR[s].y);
            *(uint2*)&As[(ar + 64 * s) * ST + ac + 4] = make_uint2(aR[s].z, aR[s].w);
            // transpose V tile into Bs[n][k]
            const __half* hp = reinterpret_cast<const __half*>(&bR[s]);
#pragma unroll
            for (int h = 0; h < 8; h++)
                Bs[(bc8 + h) * ST + bkk + 16 * s] = hp[h];
        }
        __syncthreads();
        if (kt + 1 < KT) {
            int ko = (kt + 1) * BK;
#pragma unroll
            for (int s = 0; s < 2; s++) {
                aR[s] = *(const uint4*)(Ap + (size_t)(m0 + ar + 64 * s) * S2D + ko + ac);
                bR[s] = *(const uint4*)(Bv + (size_t)(ko + bkk + 16 * s) * PDIM + n0 + bc8);
            }
        }
        mma_tile(As, Bs, wm, wn, g, t, c);
    }

#pragma unroll
    for (int i = 0; i < 2; i++)
#pragma unroll
        for (int j = 0; j < 8; j++) {
            int row = m0 + wm + 16 * i + g;
            int col = n0 + wn + 8 * j + 2 * t;
            *(float2*)(C + (size_t)row * PDIM + col) = make_float2(c[i][j][0], c[i][j][1]);
            *(float2*)(C + (size_t)(row + 8) * PDIM + col) = make_float2(c[i][j][2], c[i][j][3]);
        }
}

// ---------------- launch ----------------
extern "C" void kernel_launch(void* const* d_in, const int* in_sizes, int n_in,
                              void* d_out, int out_size) {
    const float* q = (const float*)d_in[0];
    const float* k = (const float*)d_in[1];
    const float* v = (const float*)d_in[2];
    const float* W = (const float*)d_in[3];
    const float* b = (const float*)d_in[4];
    float* out = (float*)d_out;

    convw_kernel<<<(PDIM * EDIM) / (256 * 4), 256>>>(W);

    dim3 gproj(PDIM / BN, (BATCH * S1D) / BM);  // 8 x 128
    proj_kernel<<<gproj, 256>>>(q, b, 0);
    proj_kernel<<<gproj, 256>>>(k, b, 1);
    proj_kernel<<<gproj, 256>>>(v, b, 2);

    dim3 gs(S2D / BN, S1D / BM, BATCH);  // 16 x 16 x 8
    scores_kernel<<<gs, 256>>>();

    softmax_kernel<<<BATCH * S1D, 256>>>();

    dim3 go(PDIM / BN, S1D / BM, BATCH);  // 8 x 16 x 8
    out_kernel<<<go, 256>>>(out);
}

// round 2
// speedup vs baseline: 2.1965x; 2.1965x over previous
#include <cuda_runtime.h>
#include <cuda_fp16.h>
#include <cstdint>

#define BATCH 8
#define S1D 2048
#define S2D 2048
#define EDIM 1024
#define PDIM 1024

#define BM 128
#define BN 128
#define BK 64

// ---------------- scratch ----------------
__device__ __half g_inh[(size_t)3 * BATCH * S1D * EDIM];   // q,k,v fp16 (96 MB)
__device__ __half g_outh[(size_t)3 * BATCH * S1D * PDIM];  // projected q,k,v fp16 (96 MB)
__device__ __half g_wh[(size_t)PDIM * EDIM];               // 2 MB
__device__ float  g_scores[(size_t)BATCH * S1D * S2D];     // 134 MB
__device__ __half g_probs[(size_t)BATCH * S1D * S2D];      // 67 MB

__device__ __forceinline__ void mma16816(float c[4], const uint32_t a[4], const uint32_t b[2]) {
    asm volatile(
        "mma.sync.aligned.m16n8k16.row.col.f32.f16.f16.f32 "
        "{%0,%1,%2,%3}, {%4,%5,%6,%7}, {%8,%9}, {%0,%1,%2,%3};\n"
        : "+f"(c[0]), "+f"(c[1]), "+f"(c[2]), "+f"(c[3])
        : "r"(a[0]), "r"(a[1]), "r"(a[2]), "r"(a[3]), "r"(b[0]), "r"(b[1]));
}

__device__ __forceinline__ void cp16(__half* sptr, const __half* gptr) {
    uint32_t s = (uint32_t)__cvta_generic_to_shared(sptr);
    asm volatile("cp.async.cg.shared.global [%0], [%1], 16;\n" :: "r"(s), "l"(gptr));
}
#define CP_COMMIT() asm volatile("cp.async.commit_group;\n")

__device__ __forceinline__ uint32_t h2_as_u32(__half2 h) {
    return *reinterpret_cast<uint32_t*>(&h);
}

// =================================================================================
// Shared GEMM mainloop. Block 128x128, BK=64, 8 warps (warp tile 32x64).
// A: [M][K] fp16 k-major. B: NT mode: [N][K] k-major; NN mode: [K][N] n-major.
// Smem swizzle: 16B chunk c at row r placed at chunk (c ^ (r&7)) within each 128B span.
// =================================================================================
template<int BNN>
__device__ __forceinline__ void gemm_main(const __half* __restrict__ A,
                                          const __half* __restrict__ B,
                                          int lda, int ldb, int m0, int n0, int KT,
                                          __half* sm, float c[2][8][4]) {
    const int tid = threadIdx.x;
    const int warp = tid >> 5, lane = tid & 31;
    const int wm = (warp & 3) * 32, wn = (warp >> 2) * 64;
    __half* As0 = sm;           // 2 x 8192 halves
    __half* Bs0 = sm + 16384;   // 2 x 8192 halves

    const int a_r = tid >> 3, a_c = tid & 7;       // A/B-NT: 128 rows x 8 chunks, 4 sweeps
    const int bn_r = tid >> 4, bn_c = tid & 15;    // B-NN: 64 rows x 16 chunks, 4 sweeps

#define LOAD_A(kt, buf) {                                                              \
        __half* S = As0 + (buf) * 8192;                                                \
        _Pragma("unroll")                                                              \
        for (int s = 0; s < 4; s++) {                                                  \
            int r = a_r + 32 * s;                                                      \
            cp16(S + r * 64 + ((a_c ^ (r & 7)) << 3),                                  \
                 A + (size_t)(m0 + r) * lda + (kt) * 64 + a_c * 8);                    \
        } }
#define LOAD_B(kt, buf) {                                                              \
        __half* S = Bs0 + (buf) * 8192;                                                \
        if (!BNN) {                                                                    \
            _Pragma("unroll")                                                          \
            for (int s = 0; s < 4; s++) {                                              \
                int r = a_r + 32 * s;                                                  \
                cp16(S + r * 64 + ((a_c ^ (r & 7)) << 3),                              \
                     B + (size_t)(n0 + r) * ldb + (kt) * 64 + a_c * 8);                \
            }                                                                          \
        } else {                                                                       \
            _Pragma("unroll")                                                          \
            for (int s = 0; s < 4; s++) {                                              \
                int r = bn_r + 16 * s;                                                 \
                int pc = (bn_c & 8) | ((bn_c & 7) ^ (r & 7));                          \
                cp16(S + r * 128 + (pc << 3),                                          \
                     B + (size_t)((kt) * 64 + r) * ldb + n0 + bn_c * 8);               \
            }                                                                          \
        } }

    LOAD_A(0, 0); LOAD_B(0, 0); CP_COMMIT();

    for (int kt = 0; kt < KT; kt++) {
        int buf = kt & 1;
        if (kt + 1 < KT) {
            LOAD_A(kt + 1, buf ^ 1); LOAD_B(kt + 1, buf ^ 1); CP_COMMIT();
            asm volatile("cp.async.wait_group 1;\n");
        } else {
            asm volatile("cp.async.wait_group 0;\n");
        }
        __syncthreads();

        const __half* As = As0 + buf * 8192;
        const __half* Bs = Bs0 + buf * 8192;
#pragma unroll
        for (int kk = 0; kk < 64; kk += 16) {
            uint32_t a[2][4];
#pragma unroll
            for (int i = 0; i < 2; i++) {
                int row = wm + 16 * i + (lane & 15);
                int kc = (kk >> 3) + ((lane & 16) ? 1 : 0);
                uint32_t addr = (uint32_t)__cvta_generic_to_shared(
                    As + row * 64 + ((kc ^ (row & 7)) << 3));
                asm volatile("ldmatrix.sync.aligned.m8n8.x4.shared.b16 {%0,%1,%2,%3}, [%4];\n"
                             : "=r"(a[i][0]), "=r"(a[i][1]), "=r"(a[i][2]), "=r"(a[i][3])
                             : "r"(addr));
            }
            uint32_t b[8][2];
            if (!BNN) {
#pragma unroll
                for (int l = 0; l < 4; l++) {
                    int row = wn + 16 * l + (lane & 7) + ((lane & 16) ? 8 : 0);
                    int kc = (kk >> 3) + ((lane & 8) ? 1 : 0);
                    uint32_t addr = (uint32_t)__cvta_generic_to_shared(
                        Bs + row * 64 + ((kc ^ (row & 7)) << 3));
                    asm volatile("ldmatrix.sync.aligned.m8n8.x4.shared.b16 {%0,%1,%2,%3}, [%4];\n"
                                 : "=r"(b[2 * l][0]), "=r"(b[2 * l][1]),
                                   "=r"(b[2 * l + 1][0]), "=r"(b[2 * l + 1][1])
                                 : "r"(addr));
                }
            } else {
#pragma unroll
                for (int l = 0; l < 4; l++) {
                    int row = kk + (lane & 7) + ((lane & 8) ? 8 : 0);
                    int cc = ((wn + 16 * l) >> 3) + ((lane & 16) ? 1 : 0);
                    int pc = (cc & 8) | ((cc & 7) ^ (row & 7));
                    uint32_t addr = (uint32_t)__cvta_generic_to_shared(
                        Bs + row * 128 + (pc << 3));
                    asm volatile("ldmatrix.sync.aligned.m8n8.x4.trans.shared.b16 {%0,%1,%2,%3}, [%4];\n"
                                 : "=r"(b[2 * l][0]), "=r"(b[2 * l][1]),
                                   "=r"(b[2 * l + 1][0]), "=r"(b[2 * l + 1][1])
                                 : "r"(addr));
                }
            }
#pragma unroll
            for (int i = 0; i < 2; i++)
#pragma unroll
                for (int j = 0; j < 8; j++) mma16816(c[i][j], a[i], b[j]);
        }
        __syncthreads();
    }
#undef LOAD_A
#undef LOAD_B
}

// ---------------- fp32 -> fp16 conversion ----------------
__global__ void __launch_bounds__(256) conv_kernel(const float* __restrict__ src,
                                                   __half* __restrict__ dst) {
    size_t i = ((size_t)blockIdx.x * 256 + threadIdx.x) * 8;
    float4 v0 = *(const float4*)(src + i);
    float4 v1 = *(const float4*)(src + i + 4);
    uint4 o;
    o.x = h2_as_u32(__floats2half2_rn(v0.x, v0.y));
    o.y = h2_as_u32(__floats2half2_rn(v0.z, v0.w));
    o.z = h2_as_u32(__floats2half2_rn(v1.x, v1.y));
    o.w = h2_as_u32(__floats2half2_rn(v1.z, v1.w));
    *(uint4*)(dst + i) = o;
}

// ---------------- projection: g_outh = g_inh @ W^T + bias (fp16 out) ----------------
__global__ void __launch_bounds__(256, 2) proj_kernel(const float* __restrict__ bias) {
    extern __shared__ __half sm[];
    const int m0 = blockIdx.y * BM, n0 = blockIdx.x * BN;
    float c[2][8][4] = {};
    gemm_main<0>(g_inh, g_wh, EDIM, EDIM, m0, n0, EDIM / BK, sm, c);

    const int lane = threadIdx.x & 31, warp = threadIdx.x >> 5;
    const int wm = (warp & 3) * 32, wn = (warp >> 2) * 64;
    const int g = lane >> 2, t = lane & 3;
#pragma unroll
    for (int i = 0; i < 2; i++)
#pragma unroll
        for (int j = 0; j < 8; j++) {
            int row = m0 + wm + 16 * i + g;
            int col = n0 + wn + 8 * j + 2 * t;
            float b0 = bias[col], b1 = bias[col + 1];
            *(__half2*)(g_outh + (size_t)row * PDIM + col) =
                __floats2half2_rn(c[i][j][0] + b0, c[i][j][1] + b1);
            *(__half2*)(g_outh + (size_t)(row + 8) * PDIM + col) =
                __floats2half2_rn(c[i][j][2] + b0, c[i][j][3] + b1);
        }
}

// ---------------- scores: fp32 = (Qp @ Kp^T) / 32 ----------------
__global__ void __launch_bounds__(256, 2) scores_kernel() {
    extern __shared__ __half sm[];
    const size_t z = blockIdx.z;
    const __half* A = g_outh + z * S1D * PDIM;
    const __half* B = g_outh + (size_t)BATCH * S1D * PDIM + z * S2D * PDIM;
    float* C = g_scores + z * S1D * S2D;
    const int m0 = blockIdx.y * BM, n0 = blockIdx.x * BN;
    float c[2][8][4] = {};
    gemm_main<0>(A, B, PDIM, PDIM, m0, n0, PDIM / BK, sm, c);

    const int lane = threadIdx.x & 31, warp = threadIdx.x >> 5;
    const int wm = (warp & 3) * 32, wn = (warp >> 2) * 64;
    const int g = lane >> 2, t = lane & 3;
    const float SC = 0.03125f;
#pragma unroll
    for (int i = 0; i < 2; i++)
#pragma unroll
        for (int j = 0; j < 8; j++) {
            int row = m0 + wm + 16 * i + g;
            int col = n0 + wn + 8 * j + 2 * t;
            *(float2*)(C + (size_t)row * S2D + col) =
                make_float2(c[i][j][0] * SC, c[i][j][1] * SC);
            *(float2*)(C + (size_t)(row + 8) * S2D + col) =
                make_float2(c[i][j][2] * SC, c[i][j][3] * SC);
        }
}

// ---------------- softmax over last dim (2048), fp32 in -> fp16 probs ----------------
__global__ void __launch_bounds__(256) softmax_kernel() {
    const size_t row = blockIdx.x;
    const float* src = g_scores + row * S2D;
    __half* dst = g_probs + row * S2D;
    const int tid = threadIdx.x;
    const int lane = tid & 31, warp = tid >> 5;

    float4 v0 = *(const float4*)(src + tid * 4);
    float4 v1 = *(const float4*)(src + 1024 + tid * 4);

    float m = fmaxf(fmaxf(fmaxf(v0.x, v0.y), fmaxf(v0.z, v0.w)),
                    fmaxf(fmaxf(v1.x, v1.y), fmaxf(v1.z, v1.w)));
#pragma unroll
    for (int off = 16; off > 0; off >>= 1)
        m = fmaxf(m, __shfl_xor_sync(0xffffffffu, m, off));

    __shared__ float red[8];
    __shared__ float sbc;
    if (lane == 0) red[warp] = m;
    __syncthreads();
    if (warp == 0) {
        float x = (lane < 8) ? red[lane] : -1e30f;
#pragma unroll
        for (int off = 4; off > 0; off >>= 1)
            x = fmaxf(x, __shfl_xor_sync(0xffffffffu, x, off));
        if (lane == 0) sbc = x;
    }
    __syncthreads();
    m = sbc;

    float e[8];
    e[0] = expf(v0.x - m); e[1] = expf(v0.y - m); e[2] = expf(v0.z - m); e[3] = expf(v0.w - m);
    e[4] = expf(v1.x - m); e[5] = expf(v1.y - m); e[6] = expf(v1.z - m); e[7] = expf(v1.w - m);

    float s = e[0] + e[1] + e[2] + e[3] + e[4] + e[5] + e[6] + e[7];
#pragma unroll
    for (int off = 16; off > 0; off >>= 1)
        s += __shfl_xor_sync(0xffffffffu, s, off);
    __syncthreads();
    if (lane == 0) red[warp] = s;
    __syncthreads();
    if (warp == 0) {
        float x = (lane < 8) ? red[lane] : 0.0f;
#pragma unroll
        for (int off = 4; off > 0; off >>= 1)
            x += __shfl_xor_sync(0xffffffffu, x, off);
        if (lane == 0) sbc = x;
    }
    __syncthreads();
    float inv = 1.0f / sbc;

    uint2 o0, o1;
    o0.x = h2_as_u32(__floats2half2_rn(e[0] * inv, e[1] * inv));
    o0.y = h2_as_u32(__floats2half2_rn(e[2] * inv, e[3] * inv));
    o1.x = h2_as_u32(__floats2half2_rn(e[4] * inv, e[5] * inv));
    o1.y = h2_as_u32(__floats2half2_rn(e[6] * inv, e[7] * inv));
    *(uint2*)(dst + tid * 4) = o0;
    *(uint2*)(dst + 1024 + tid * 4) = o1;
}

// ---------------- output: O = probs @ Vp  (NN gemm via ldmatrix.trans) ----------------
__global__ void __launch_bounds__(256, 2) out_kernel(float* __restrict__ OUT) {
    extern __shared__ __half sm[];
    const size_t z = blockIdx.z;
    const __half* A = g_probs + z * S1D * S2D;
    const __half* B = g_outh + (size_t)2 * BATCH * S1D * PDIM + z * S2D * PDIM;
    float* C = OUT + z * S1D * PDIM;
    const int m0 = blockIdx.y * BM, n0 = blockIdx.x * BN;
    float c[2][8][4] = {};
    gemm_main<1>(A, B, S2D, PDIM, m0, n0, S2D / BK, sm, c);

    const int lane = threadIdx.x & 31, warp = threadIdx.x >> 5;
    const int wm = (warp & 3) * 32, wn = (warp >> 2) * 64;
    const int g = lane >> 2, t = lane & 3;
#pragma unroll
    for (int i = 0; i < 2; i++)
#pragma unroll
        for (int j = 0; j < 8; j++) {
            int row = m0 + wm + 16 * i + g;
            int col = n0 + wn + 8 * j + 2 * t;
            *(float2*)(C + (size_t)row * PDIM + col) = make_float2(c[i][j][0], c[i][j][1]);
            *(float2*)(C + (size_t)(row + 8) * PDIM + col) = make_float2(c[i][j][2], c[i][j][3]);
        }
}

// ---------------- launch ----------------
extern "C" void kernel_launch(void* const* d_in, const int* in_sizes, int n_in,
                              void* d_out, int out_size) {
    const float* q = (const float*)d_in[0];
    const float* k = (const float*)d_in[1];
    const float* v = (const float*)d_in[2];
    const float* W = (const float*)d_in[3];
    const float* b = (const float*)d_in[4];
    float* out = (float*)d_out;

    static bool attr_done = false;
    if (!attr_done) {
        cudaFuncSetAttribute(proj_kernel, cudaFuncAttributeMaxDynamicSharedMemorySize, 65536);
        cudaFuncSetAttribute(scores_kernel, cudaFuncAttributeMaxDynamicSharedMemorySize, 65536);
        cudaFuncSetAttribute(out_kernel, cudaFuncAttributeMaxDynamicSharedMemorySize, 65536);
        attr_done = true;
    }

    __half* inh;
    __half* wh;
    cudaGetSymbolAddress((void**)&inh, g_inh);
    cudaGetSymbolAddress((void**)&wh, g_wh);

    const size_t NT = (size_t)BATCH * S1D * EDIM;  // 16.7M per tensor
    conv_kernel<<<NT / (256 * 8), 256>>>(q, inh);
    conv_kernel<<<NT / (256 * 8), 256>>>(k, inh + NT);
    conv_kernel<<<NT / (256 * 8), 256>>>(v, inh + 2 * NT);
    conv_kernel<<<(PDIM * EDIM) / (256 * 8), 256>>>(W, wh);

    dim3 gproj(PDIM / BN, (3 * BATCH * S1D) / BM);  // 8 x 384
    proj_kernel<<<gproj, 256, 65536>>>(b);

    dim3 gs(S2D / BN, S1D / BM, BATCH);  // 16 x 16 x 8
    scores_kernel<<<gs, 256, 65536>>>();

    softmax_kernel<<<BATCH * S1D, 256>>>();

    dim3 go(PDIM / BN, S1D / BM, BATCH);  // 8 x 16 x 8
    out_kernel<<<go, 256, 65536>>>(out);
}